// round 14
// baseline (speedup 1.0000x reference)
#include <cuda_runtime.h>
#include <math_constants.h>
#include <cstdint>

#define N_TOK 131072
#define IN_F  128
#define OUT_F 256
#define NEXP  8
#define OMEGA 30.0f

#define TM 128
#define TH 512

// ---- smem layout (bytes). A tiles: [128 rows][128 k + 16 pad] int8
#define SROW 144
#define AX1 0
#define AX0 18432
#define AL1 36864
#define AL0 55296
#define BB  73728          // B buffers base
#define BMT 4608           // one B matrix tile: 32 n-rows * 144
#define BCH 27648          // one ct chunk: 6 tiles
#define SMEM_BYTES (BB + 3 * BCH)   // 156672

// ---------------- scratch ----------------
__device__ int      g_count[NEXP];
__device__ int      g_tok[NEXP * N_TOK];     // (slot<<24) | token
__device__ float    g_wt [NEXP * N_TOK];
__device__ float    g_part[N_TOK][OUT_F];    // slot-1 contributions only
__device__ uint32_t g_re[N_TOK];
__device__ float    g_w0[N_TOK];
__device__ int      g_amax[2];               // abs-max bits: x, lat
__device__ int      g_wamax[NEXP * 3];       // abs-max bits per (e,d)
// quantized weights: [e][d][split][n=256][k=128] int8
__device__ __align__(128) char g_wq[NEXP * 3 * 2 * 256 * 128];

// ---------------- PTX helpers ----------------
__device__ __forceinline__ uint32_t smem_u32(const void* p) {
    uint32_t a;
    asm("{ .reg .u64 t; cvta.to.shared.u64 t, %1; cvt.u32.u64 %0, t; }" : "=r"(a) : "l"(p));
    return a;
}
__device__ __forceinline__ void ldsm_x4(uint32_t* r, uint32_t addr) {
    asm volatile("ldmatrix.sync.aligned.m8n8.x4.shared.b16 {%0,%1,%2,%3}, [%4];"
        : "=r"(r[0]), "=r"(r[1]), "=r"(r[2]), "=r"(r[3]) : "r"(addr));
}
__device__ __forceinline__ void mma_s8(int (&c)[4], const uint32_t (&a)[4],
                                       uint32_t b0, uint32_t b1) {
    asm volatile("mma.sync.aligned.m16n8k32.row.col.s32.s8.s8.s32 "
        "{%0,%1,%2,%3}, {%4,%5,%6,%7}, {%8,%9}, {%0,%1,%2,%3};"
        : "+r"(c[0]), "+r"(c[1]), "+r"(c[2]), "+r"(c[3])
        : "r"(a[0]), "r"(a[1]), "r"(a[2]), "r"(a[3]), "r"(b0), "r"(b1));
}
__device__ __forceinline__ void cp16(uint32_t dst, const void* src) {
    asm volatile("cp.async.cg.shared.global [%0], [%1], 16;"
                 :: "r"(dst), "l"(src) : "memory");
}
// quantize v -> hi*128 + lo (14-bit fixed point)
__device__ __forceinline__ void q2(float v, float i128, float s128, float inv,
                                   int& hi, int& lo) {
    hi = __float2int_rn(v * i128);
    float r = fmaf((float)(-hi), s128, v);
    lo = __float2int_rn(r * inv);
}
__device__ __forceinline__ uint32_t pack4(int a, int b, int c, int d) {
    return (uint32_t)(a & 255) | ((uint32_t)(b & 255) << 8)
         | ((uint32_t)(c & 255) << 16) | ((uint32_t)d << 24);
}

// ---------------- kernel 0: init + weight abs-max (fused) ----------------
__global__ void initw_kernel(const float* __restrict__ W,
                             const float* __restrict__ Wl) {
    if (blockIdx.x == 0) {
        if (threadIdx.x < NEXP) g_count[threadIdx.x] = 0;
        else if (threadIdx.x < NEXP + 2) g_amax[threadIdx.x - NEXP] = 0;
    }
    __shared__ float smax[256];
    int t = blockIdx.x, e = t / 3, d = t % 3;
    const float* src = (d == 0) ? W + (size_t)e * IN_F * OUT_F
                                : Wl + (size_t)e * IN_F * 2 * OUT_F + (d == 2 ? OUT_F : 0);
    int ldm = (d == 0) ? OUT_F : 2 * OUT_F;
    float m = 0.0f;
    for (int k = 0; k < IN_F; k++)
        m = fmaxf(m, fabsf(src[(size_t)k * ldm + threadIdx.x]));
    smax[threadIdx.x] = m;
    __syncthreads();
    for (int s = 128; s; s >>= 1) {
        if (threadIdx.x < s) smax[threadIdx.x] = fmaxf(smax[threadIdx.x], smax[threadIdx.x + s]);
        __syncthreads();
    }
    if (threadIdx.x == 0) g_wamax[t] = __float_as_int(smax[0]);
}

// ---------------- kernel 1: lane-specialized routing + amax + passthrough ----------------
// lane l -> expert (l&7), k-chunk (l>>3). 8 LDS.128 + 32 FMA + ~21 shfl per token.
__global__ void route_kernel(const float* __restrict__ x,
                             const float* __restrict__ lat,
                             const float* __restrict__ gw,
                             const float* __restrict__ gb,
                             float* __restrict__ out) {
    __shared__ float s_gwt[NEXP][IN_F + 4];
    __shared__ float s_gb[NEXP];
    __shared__ float s_xm[8], s_lm[8];
    int tid = threadIdx.x;
#pragma unroll
    for (int i = 0; i < IN_F * NEXP / 256; i++) {
        int idx = i * 256 + tid;
        int e = idx & 7, k = idx >> 3;
        s_gwt[e][k] = gw[idx];
    }
    if (tid < NEXP) s_gb[tid] = gb[tid];
    __syncthreads();

    int warp = tid >> 5, lane = tid & 31;
    int t = blockIdx.x * 8 + warp;
    int el = lane & 7, c = lane >> 3;

    // latents: amax + passthrough to output tail
    float4 lv = *(const float4*)(lat + (size_t)t * IN_F + lane * 4);
    *(float4*)(out + (size_t)N_TOK * OUT_F + (size_t)t * IN_F + lane * 4) = lv;
    float lm = fmaxf(fmaxf(fabsf(lv.x), fabsf(lv.y)), fmaxf(fabsf(lv.z), fabsf(lv.w)));

    // gate dot: this lane covers expert el over k-chunk c (32 values)
    const float4* xr = (const float4*)(x + (size_t)t * IN_F + c * 32);
    const float4* gr = (const float4*)(&s_gwt[el][c * 32]);
    float p = 0.0f, xm = 0.0f;
#pragma unroll
    for (int j = 0; j < 8; j++) {
        float4 xv = xr[j];
        float4 g4 = gr[j];
        p = fmaf(xv.x, g4.x, p);
        p = fmaf(xv.y, g4.y, p);
        p = fmaf(xv.z, g4.z, p);
        p = fmaf(xv.w, g4.w, p);
        xm = fmaxf(xm, fmaxf(fmaxf(fabsf(xv.x), fabsf(xv.y)),
                             fmaxf(fabsf(xv.z), fabsf(xv.w))));
    }
    // combine k-chunks (lane bits 3,4)
    p += __shfl_xor_sync(0xffffffffu, p, 8);
    p += __shfl_xor_sync(0xffffffffu, p, 16);
    xm = fmaxf(xm, __shfl_xor_sync(0xffffffffu, xm, 8));
    xm = fmaxf(xm, __shfl_xor_sync(0xffffffffu, xm, 16));
#pragma unroll
    for (int off = 16; off; off >>= 1)
        lm = fmaxf(lm, __shfl_xor_sync(0xffffffffu, lm, off));
    p += s_gb[el];

    // top-2 butterfly merge over the 8-expert lanes (offsets 4,2,1).
    // merging (best,sec) with other lane's (ob,os), os <= ob always:
    //   ob >  best: new pair = (ob, max(best, os))
    //   ob <= best: new pair = (best, max(sec, ob))   [os <= ob, so os can't win]
    float best = p, sec = -CUDART_INF_F;
    int bi = el, si = el;
#pragma unroll
    for (int off = 4; off; off >>= 1) {
        float ob = __shfl_xor_sync(0xffffffffu, best, off);
        int   obi = __shfl_xor_sync(0xffffffffu, bi, off);
        float os = __shfl_xor_sync(0xffffffffu, sec, off);
        int   osi = __shfl_xor_sync(0xffffffffu, si, off);
        if (ob > best) {
            if (best > os) { sec = best; si = bi; }
            else           { sec = os;   si = osi; }
            best = ob; bi = obi;
        } else if (ob > sec) {
            sec = ob; si = obi;
        }
    }

    if (lane == 0) {
        s_xm[warp] = xm;
        s_lm[warp] = lm;
        g_re[t] = (uint32_t)bi | ((uint32_t)si << 8);
        g_w0[t] = 1.0f / (1.0f + expf(sec - best));
    }
    __syncthreads();
    if (tid == 0) {
        float mx = s_xm[0], ml = s_lm[0];
#pragma unroll
        for (int i = 1; i < 8; i++) {
            mx = fmaxf(mx, s_xm[i]);
            ml = fmaxf(ml, s_lm[i]);
        }
        atomicMax(&g_amax[0], __float_as_int(mx));
        atomicMax(&g_amax[1], __float_as_int(ml));
    }
}

// ---------------- kernel 1a: hierarchical scatter ----------------
__global__ void scatter_kernel() {
    __shared__ int scnt[NEXP], sbase[NEXP];
    int tid = threadIdx.x;
    if (tid < NEXP) scnt[tid] = 0;
    __syncthreads();
    int base_t = blockIdx.x * 4096;
    int lr0[16], lr1[16];
#pragma unroll
    for (int r = 0; r < 16; r++) {
        int t = base_t + r * 256 + tid;
        uint32_t re = g_re[t];
        lr0[r] = atomicAdd(&scnt[re & 255], 1);
        lr1[r] = atomicAdd(&scnt[(re >> 8) & 255], 1);
    }
    __syncthreads();
    if (tid < NEXP) sbase[tid] = atomicAdd(&g_count[tid], scnt[tid]);
    __syncthreads();
#pragma unroll
    for (int r = 0; r < 16; r++) {
        int t = base_t + r * 256 + tid;
        uint32_t re = g_re[t];
        float w0 = g_w0[t];
        int e0 = re & 255, e1 = (re >> 8) & 255;
        int p0 = sbase[e0] + lr0[r];
        int p1 = sbase[e1] + lr1[r];
        g_tok[e0 * N_TOK + p0] = t;
        g_wt [e0 * N_TOK + p0] = w0;
        g_tok[e1 * N_TOK + p1] = t | (1 << 24);
        g_wt [e1 * N_TOK + p1] = 1.0f - w0;
    }
}

// ---------------- kernel 1b: quantize weights to int8 [n][k] ----------------
__global__ void wq_kernel(const float* __restrict__ W,
                          const float* __restrict__ Wl) {
    int idx = blockIdx.x * 256 + threadIdx.x;    // 196608
    int n = idx & 255;
    int kq = (idx >> 8) & 31;
    int rest = idx >> 13;
    int d = rest % 3, e = rest / 3;
    const float* src = (d == 0)
        ? W  + (size_t)e * IN_F * OUT_F + n
        : Wl + (size_t)e * IN_F * 2 * OUT_F + (d == 2 ? OUT_F : 0) + n;
    int ldm = (d == 0) ? OUT_F : 2 * OUT_F;

    float am = fmaxf(__int_as_float(g_wamax[e * 3 + d]), 1e-20f);
    float alpha = am * (1.0001f / 16256.0f);
    float inv = 1.0f / alpha, s128 = 128.0f * alpha, i128 = inv * (1.0f / 128.0f);

    int hi[4], lo[4];
#pragma unroll
    for (int j = 0; j < 4; j++) {
        float v = src[(size_t)(kq * 4 + j) * ldm];
        q2(v, i128, s128, inv, hi[j], lo[j]);
    }
    size_t base = (((size_t)((e * 3 + d) * 2) * 256) + n) * 128 + kq * 4;
    *(uint32_t*)&g_wq[base]             = pack4(hi[0], hi[1], hi[2], hi[3]);
    *(uint32_t*)&g_wq[base + 256 * 128] = pack4(lo[0], lo[1], lo[2], lo[3]);
}

// ---------------- kernel 2: int8 3-product mma pipeline + fused sin ----------------
// 16 warps: mi = w>>1 (16-row band), ni = w&1 (16-col half of the 32-col ctile)
__global__ __launch_bounds__(TH, 1) void expert_kernel(
    const float* __restrict__ x,  const float* __restrict__ lat,
    const float* __restrict__ b,  const float* __restrict__ bl,
    float* __restrict__ out)
{
    extern __shared__ __align__(16) char sm[];
    __shared__ int   s_ent[TM];
    __shared__ float s_w[TM];

    int e = blockIdx.y;
    int cnt = g_count[e];
    int m0 = blockIdx.x * TM;
    if (m0 >= cnt) return;
    int rows = min(TM, cnt - m0);
    int tid = threadIdx.x;
    int w = tid >> 5, lane = tid & 31;

    uint32_t smu = smem_u32(sm);
    const char* wqe = g_wq + (size_t)(e * 6) * 256 * 128;

    // scales
    float ax = fmaxf(__int_as_float(g_amax[0]), 1e-20f) * (1.0001f / 16256.0f);
    float al = fmaxf(__int_as_float(g_amax[1]), 1e-20f) * (1.0001f / 16256.0f);
    float aw[3];
#pragma unroll
    for (int d = 0; d < 3; d++)
        aw[d] = fmaxf(__int_as_float(g_wamax[e * 3 + d]), 1e-20f) * (1.0001f / 16256.0f);

    // ---- issue cp.async for ct 0,1 (buf 0,1)
#pragma unroll
    for (int j = 0; j < 2; j++) {
#pragma unroll
        for (int t = 0; t < 3; t++) {
            int u = t * TH + tid;                 // 0..1535
            int mat = u >> 8, rem = u & 255;
            int n = rem >> 3, k16 = rem & 7;
            cp16(smu + BB + (uint32_t)(j * BCH + mat * BMT + n * SROW + k16 * 16),
                 wqe + ((size_t)mat * 256 + j * 32 + n) * 128 + k16 * 16);
        }
        asm volatile("cp.async.commit_group;" ::: "memory");
    }

    if (tid < TM) {
        int ent = (tid < rows) ? g_tok[e * N_TOK + m0 + tid] : 0;
        s_ent[tid] = ent;
        s_w[tid]   = (tid < rows) ? g_wt[e * N_TOK + m0 + tid] : 0.0f;
    }
    __syncthreads();

    // ---- stage A: gather x/lat rows, quantize to int8 hi/lo
#pragma unroll
    for (int s2 = 0; s2 < 2; s2++) {
        const float* src = s2 ? lat : x;
        float alpha = s2 ? al : ax;
        float inv = 1.0f / alpha, s128 = 128.0f * alpha, i128 = inv * (1.0f / 128.0f);
        char* hiT = sm + (s2 ? AL1 : AX1);
        char* loT = sm + (s2 ? AL0 : AX0);
#pragma unroll
        for (int it = 0; it < 8; it++) {
            int idx = it * TH + tid;              // 0..4095
            int m = idx >> 5, kg = (idx & 31) * 4;
            int tok = s_ent[m] & 0xFFFFFF;
            float4 v = *(const float4*)(src + (size_t)tok * IN_F + kg);
            int h0, l0, h1, l1, h2, l2, h3, l3;
            q2(v.x, i128, s128, inv, h0, l0);
            q2(v.y, i128, s128, inv, h1, l1);
            q2(v.z, i128, s128, inv, h2, l2);
            q2(v.w, i128, s128, inv, h3, l3);
            *(uint32_t*)(hiT + m * SROW + kg) = pack4(h0, h1, h2, h3);
            *(uint32_t*)(loT + m * SROW + kg) = pack4(l0, l1, l2, l3);
        }
    }

    int mi = w >> 1, ni = w & 1;
    uint32_t lrow = (uint32_t)((lane & 7) + ((lane >> 3) & 1) * 8);
    uint32_t lcol = (uint32_t)((lane >> 4) * 16);
    uint32_t aof = (uint32_t)(mi * 16 + lrow) * SROW + lcol;
    uint32_t bof = (uint32_t)(ni * 16 + lrow) * SROW + lcol;

    // dequant constants: contribution = 128*s*(128*aS + aM); OMEGA folded into d0
    float c128[3];
#pragma unroll
    for (int d = 0; d < 3; d++) {
        float s = (d == 0 ? ax : al) * aw[d];
        if (d == 0) s *= OMEGA;
        c128[d] = 128.0f * s;
    }

#pragma unroll 1
    for (int ct = 0; ct < 8; ct++) {
        if (ct == 7) asm volatile("cp.async.wait_group 0;" ::: "memory");
        else         asm volatile("cp.async.wait_group 1;" ::: "memory");
        __syncthreads();   // buf (ct-1)%3 now reusable

        if (ct <= 5) {
            int j = ct + 2, buf2 = j % 3;
#pragma unroll
            for (int t = 0; t < 3; t++) {
                int u = t * TH + tid;
                int mat = u >> 8, rem = u & 255;
                int n = rem >> 3, k16 = rem & 7;
                cp16(smu + BB + (uint32_t)(buf2 * BCH + mat * BMT + n * SROW + k16 * 16),
                     wqe + ((size_t)mat * 256 + j * 32 + n) * 128 + k16 * 16);
            }
            asm volatile("cp.async.commit_group;" ::: "memory");
        }

        uint32_t bB = smu + BB + (uint32_t)(ct % 3) * BCH;
        int aS[3][2][4], aM[3][2][4];
#pragma unroll
        for (int d = 0; d < 3; d++)
#pragma unroll
            for (int nf = 0; nf < 2; nf++)
#pragma unroll
                for (int q = 0; q < 4; q++) { aS[d][nf][q] = 0; aM[d][nf][q] = 0; }

#pragma unroll
        for (int kc = 0; kc < 4; kc++) {
            uint32_t kb = (uint32_t)(kc * 32);
            uint32_t X1[4], X0[4], L1[4], L0[4];
            ldsm_x4(X1, smu + AX1 + aof + kb);
            ldsm_x4(X0, smu + AX0 + aof + kb);
            ldsm_x4(L1, smu + AL1 + aof + kb);
            ldsm_x4(L0, smu + AL0 + aof + kb);
#pragma unroll
            for (int d = 0; d < 3; d++) {
                uint32_t B1[4], B0[4];
                ldsm_x4(B1, bB + (uint32_t)(d * 2) * BMT + bof + kb);
                ldsm_x4(B0, bB + (uint32_t)(d * 2 + 1) * BMT + bof + kb);
                const uint32_t (&A1)[4] = d ? L1 : X1;
                const uint32_t (&A0)[4] = d ? L0 : X0;
                mma_s8(aS[d][0], A1, B1[0], B1[2]);
                mma_s8(aM[d][0], A1, B0[0], B0[2]);
                mma_s8(aM[d][0], A0, B1[0], B1[2]);
                mma_s8(aS[d][1], A1, B1[1], B1[3]);
                mma_s8(aM[d][1], A1, B0[1], B0[3]);
                mma_s8(aM[d][1], A0, B1[1], B1[3]);
            }
        }

        // ---- epilogue: IMAD-combine dequant + MUFU sin + gate weight
        {
            int cb0 = ct * 32 + ni * 16 + 2 * (lane & 3);
            float bb[2][2], bs[2][2], bt[2][2];
#pragma unroll
            for (int nf = 0; nf < 2; nf++) {
                float2 B  = *(const float2*)(b  + (size_t)e * OUT_F + cb0 + nf * 8);
                float2 S  = *(const float2*)(bl + (size_t)e * 2 * OUT_F + cb0 + nf * 8);
                float2 T  = *(const float2*)(bl + (size_t)e * 2 * OUT_F + OUT_F + cb0 + nf * 8);
                bb[nf][0] = B.x * OMEGA;
                bb[nf][1] = B.y * OMEGA;
                bs[nf][0] = S.x;
                bs[nf][1] = S.y;
                bt[nf][0] = T.x;
                bt[nf][1] = T.y;
            }
#pragma unroll
            for (int hh = 0; hh < 2; hh++) {
                int row = mi * 16 + (lane >> 2) + 8 * hh;
                if (row < rows) {
                    int ent = s_ent[row];
                    int tok = ent & 0xFFFFFF, sl = (ent >> 24) & 1;
                    float wt = s_w[row];
                    float* gp = sl ? &g_part[tok][cb0]
                                   : out + (size_t)tok * OUT_F + cb0;
#pragma unroll
                    for (int nf = 0; nf < 2; nf++) {
                        float2 o;
#pragma unroll
                        for (int q = 0; q < 2; q++) {
                            int i2 = 2 * hh + q;
                            int C0 = aS[0][nf][i2] * 128 + aM[0][nf][i2];
                            int C1 = aS[1][nf][i2] * 128 + aM[1][nf][i2];
                            int C2 = aS[2][nf][i2] * 128 + aM[2][nf][i2];
                            float hv30 = fmaf(__int2float_rn(C0), c128[0], bb[nf][q]);
                            float sc   = fmaf(__int2float_rn(C1), c128[1], bs[nf][q]);
                            float sh   = fmaf(__int2float_rn(C2), c128[2], bt[nf][q]);
                            float ov = wt * __sinf(fmaf(hv30, sc, sh));
                            if (q) o.y = ov; else o.x = ov;
                        }
                        *(float2*)(gp + nf * 8) = o;
                    }
                }
            }
        }
    }
}

// ---------------- kernel 3: combine (out += slot-1 partial) ----------------
__global__ void combine_kernel(float* __restrict__ out) {
    size_t i = (size_t)blockIdx.x * blockDim.x + threadIdx.x;
    const float4* p1 = (const float4*)&g_part[0][0];
    float4 a = ((const float4*)out)[i];
    float4 c = p1[i];
    ((float4*)out)[i] = make_float4(a.x + c.x, a.y + c.y, a.z + c.z, a.w + c.w);
}

// ---------------- launch ----------------
extern "C" void kernel_launch(void* const* d_in, const int* in_sizes, int n_in,
                              void* d_out, int out_size) {
    const float* x   = (const float*)d_in[0];
    const float* lat = (const float*)d_in[1];
    const float* gw  = (const float*)d_in[2];
    const float* gb  = (const float*)d_in[3];
    const float* W   = (const float*)d_in[4];
    const float* b   = (const float*)d_in[5];
    const float* Wl  = (const float*)d_in[6];
    const float* bl  = (const float*)d_in[7];
    float* out = (float*)d_out;

    cudaFuncSetAttribute(expert_kernel,
                         cudaFuncAttributeMaxDynamicSharedMemorySize, SMEM_BYTES);

    initw_kernel<<<24, 256>>>(W, Wl);
    route_kernel<<<N_TOK / 8, 256>>>(x, lat, gw, gb, out);
    scatter_kernel<<<32, 256>>>();
    wq_kernel<<<768, 256>>>(W, Wl);
    expert_kernel<<<dim3(N_TOK / TM, NEXP), TH, SMEM_BYTES>>>(x, lat, b, bl, out);
    combine_kernel<<<(N_TOK * OUT_F / 4) / 256, 256>>>(out);
}

// round 15
// speedup vs baseline: 1.0190x; 1.0190x over previous
#include <cuda_runtime.h>
#include <math_constants.h>
#include <cstdint>

#define N_TOK 131072
#define IN_F  128
#define OUT_F 256
#define NEXP  8
#define OMEGA 30.0f

#define TM 128
#define TH 512

// ---- smem layout (bytes). A tiles: [128 rows][128 k + 16 pad] int8
#define SROW 144
#define AX1 0
#define AX0 18432
#define AL1 36864
#define AL0 55296
#define BB  73728          // B buffers base
#define BMT 4608           // one B matrix tile: 32 n-rows * 144
#define BCH 27648          // one ct chunk: 6 tiles
#define SMEM_BYTES (BB + 3 * BCH)   // 156672

// ---------------- scratch ----------------
__device__ int      g_count[NEXP];
__device__ int      g_tok[NEXP * N_TOK];     // (slot<<24) | token
__device__ float    g_wt [NEXP * N_TOK];
__device__ float    g_part[N_TOK][OUT_F];    // slot-1 contributions only
__device__ uint32_t g_re[N_TOK];
__device__ float    g_w0[N_TOK];
__device__ int      g_amax[2];               // abs-max bits: x, lat
__device__ int      g_wamax[NEXP * 3];       // abs-max bits per (e,d)
// quantized weights: [e][d][split][n=256][k=128] int8
__device__ __align__(128) char g_wq[NEXP * 3 * 2 * 256 * 128];

// ---------------- PTX helpers ----------------
__device__ __forceinline__ uint32_t smem_u32(const void* p) {
    uint32_t a;
    asm("{ .reg .u64 t; cvta.to.shared.u64 t, %1; cvt.u32.u64 %0, t; }" : "=r"(a) : "l"(p));
    return a;
}
__device__ __forceinline__ void ldsm_x4(uint32_t* r, uint32_t addr) {
    asm volatile("ldmatrix.sync.aligned.m8n8.x4.shared.b16 {%0,%1,%2,%3}, [%4];"
        : "=r"(r[0]), "=r"(r[1]), "=r"(r[2]), "=r"(r[3]) : "r"(addr));
}
__device__ __forceinline__ void mma_s8(int (&c)[4], const uint32_t (&a)[4],
                                       uint32_t b0, uint32_t b1) {
    asm volatile("mma.sync.aligned.m16n8k32.row.col.s32.s8.s8.s32 "
        "{%0,%1,%2,%3}, {%4,%5,%6,%7}, {%8,%9}, {%0,%1,%2,%3};"
        : "+r"(c[0]), "+r"(c[1]), "+r"(c[2]), "+r"(c[3])
        : "r"(a[0]), "r"(a[1]), "r"(a[2]), "r"(a[3]), "r"(b0), "r"(b1));
}
__device__ __forceinline__ void cp16(uint32_t dst, const void* src) {
    asm volatile("cp.async.cg.shared.global [%0], [%1], 16;"
                 :: "r"(dst), "l"(src) : "memory");
}
// quantize v -> hi*128 + lo (14-bit fixed point)
__device__ __forceinline__ void q2(float v, float i128, float s128, float inv,
                                   int& hi, int& lo) {
    hi = __float2int_rn(v * i128);
    float r = fmaf((float)(-hi), s128, v);
    lo = __float2int_rn(r * inv);
}
__device__ __forceinline__ uint32_t pack4(int a, int b, int c, int d) {
    return (uint32_t)(a & 255) | ((uint32_t)(b & 255) << 8)
         | ((uint32_t)(c & 255) << 16) | ((uint32_t)d << 24);
}

// ---------------- kernel 0: init + weight abs-max (fused) ----------------
__global__ void initw_kernel(const float* __restrict__ W,
                             const float* __restrict__ Wl) {
    if (blockIdx.x == 0) {
        if (threadIdx.x < NEXP) g_count[threadIdx.x] = 0;
        else if (threadIdx.x < NEXP + 2) g_amax[threadIdx.x - NEXP] = 0;
    }
    __shared__ float smax[256];
    int t = blockIdx.x, e = t / 3, d = t % 3;
    const float* src = (d == 0) ? W + (size_t)e * IN_F * OUT_F
                                : Wl + (size_t)e * IN_F * 2 * OUT_F + (d == 2 ? OUT_F : 0);
    int ldm = (d == 0) ? OUT_F : 2 * OUT_F;
    float m = 0.0f;
    for (int k = 0; k < IN_F; k++)
        m = fmaxf(m, fabsf(src[(size_t)k * ldm + threadIdx.x]));
    smax[threadIdx.x] = m;
    __syncthreads();
    for (int s = 128; s; s >>= 1) {
        if (threadIdx.x < s) smax[threadIdx.x] = fmaxf(smax[threadIdx.x], smax[threadIdx.x + s]);
        __syncthreads();
    }
    if (threadIdx.x == 0) g_wamax[t] = __float_as_int(smax[0]);
}

// ---------------- kernel 1: routing + input amax + latents passthrough ----------------
// (R11 form: one x read per lane, transposed gate weights, serial top-2 at lane 0)
__global__ void route_kernel(const float* __restrict__ x,
                             const float* __restrict__ lat,
                             const float* __restrict__ gw,
                             const float* __restrict__ gb,
                             float* __restrict__ out) {
    __shared__ float s_gwt[NEXP][IN_F + 4];
    __shared__ float s_gb[NEXP];
    __shared__ float s_xm[8], s_lm[8];
    int tid = threadIdx.x;
#pragma unroll
    for (int i = 0; i < IN_F * NEXP / 256; i++) {
        int idx = i * 256 + tid;
        int e = idx & 7, k = idx >> 3;
        s_gwt[e][k] = gw[idx];
    }
    if (tid < NEXP) s_gb[tid] = gb[tid];
    __syncthreads();

    int warp = tid >> 5, lane = tid & 31;
    int t = blockIdx.x * 8 + warp;

    float4 xv = *(const float4*)(x + (size_t)t * IN_F + lane * 4);
    // latents: amax + passthrough to output tail
    float4 lv = *(const float4*)(lat + (size_t)t * IN_F + lane * 4);
    *(float4*)(out + (size_t)N_TOK * OUT_F + (size_t)t * IN_F + lane * 4) = lv;
    float xm = fmaxf(fmaxf(fabsf(xv.x), fabsf(xv.y)), fmaxf(fabsf(xv.z), fabsf(xv.w)));
    float lm = fmaxf(fmaxf(fabsf(lv.x), fabsf(lv.y)), fmaxf(fabsf(lv.z), fabsf(lv.w)));

    float p[NEXP];
#pragma unroll
    for (int e = 0; e < NEXP; e++) {
        float4 g4 = *(const float4*)&s_gwt[e][lane * 4];
        float acc = xv.x * g4.x;
        acc = fmaf(xv.y, g4.y, acc);
        acc = fmaf(xv.z, g4.z, acc);
        acc = fmaf(xv.w, g4.w, acc);
        p[e] = acc;
    }
#pragma unroll
    for (int off = 16; off; off >>= 1) {
#pragma unroll
        for (int e = 0; e < NEXP; e++)
            p[e] += __shfl_xor_sync(0xffffffffu, p[e], off);
        xm = fmaxf(xm, __shfl_xor_sync(0xffffffffu, xm, off));
        lm = fmaxf(lm, __shfl_xor_sync(0xffffffffu, lm, off));
    }

    if (lane == 0) {
        s_xm[warp] = xm;
        s_lm[warp] = lm;
        float best = -CUDART_INF_F, sec = -CUDART_INF_F;
        int bi = 0, si = 0;
#pragma unroll
        for (int e = 0; e < NEXP; e++) {
            float v = p[e] + s_gb[e];
            if (v > best) { sec = best; si = bi; best = v; bi = e; }
            else if (v > sec) { sec = v; si = e; }
        }
        g_re[t] = (uint32_t)bi | ((uint32_t)si << 8);
        g_w0[t] = 1.0f / (1.0f + expf(sec - best));
    }
    __syncthreads();
    if (tid == 0) {
        float mx = s_xm[0], ml = s_lm[0];
#pragma unroll
        for (int i = 1; i < 8; i++) {
            mx = fmaxf(mx, s_xm[i]);
            ml = fmaxf(ml, s_lm[i]);
        }
        atomicMax(&g_amax[0], __float_as_int(mx));
        atomicMax(&g_amax[1], __float_as_int(ml));
    }
}

// ---------------- kernel 1a: hierarchical scatter ----------------
__global__ void scatter_kernel() {
    __shared__ int scnt[NEXP], sbase[NEXP];
    int tid = threadIdx.x;
    if (tid < NEXP) scnt[tid] = 0;
    __syncthreads();
    int base_t = blockIdx.x * 4096;
    int lr0[16], lr1[16];
#pragma unroll
    for (int r = 0; r < 16; r++) {
        int t = base_t + r * 256 + tid;
        uint32_t re = g_re[t];
        lr0[r] = atomicAdd(&scnt[re & 255], 1);
        lr1[r] = atomicAdd(&scnt[(re >> 8) & 255], 1);
    }
    __syncthreads();
    if (tid < NEXP) sbase[tid] = atomicAdd(&g_count[tid], scnt[tid]);
    __syncthreads();
#pragma unroll
    for (int r = 0; r < 16; r++) {
        int t = base_t + r * 256 + tid;
        uint32_t re = g_re[t];
        float w0 = g_w0[t];
        int e0 = re & 255, e1 = (re >> 8) & 255;
        int p0 = sbase[e0] + lr0[r];
        int p1 = sbase[e1] + lr1[r];
        g_tok[e0 * N_TOK + p0] = t;
        g_wt [e0 * N_TOK + p0] = w0;
        g_tok[e1 * N_TOK + p1] = t | (1 << 24);
        g_wt [e1 * N_TOK + p1] = 1.0f - w0;
    }
}

// ---------------- kernel 1b: quantize weights to int8 [n][k] ----------------
__global__ void wq_kernel(const float* __restrict__ W,
                          const float* __restrict__ Wl) {
    int idx = blockIdx.x * 256 + threadIdx.x;    // 196608
    int n = idx & 255;
    int kq = (idx >> 8) & 31;
    int rest = idx >> 13;
    int d = rest % 3, e = rest / 3;
    const float* src = (d == 0)
        ? W  + (size_t)e * IN_F * OUT_F + n
        : Wl + (size_t)e * IN_F * 2 * OUT_F + (d == 2 ? OUT_F : 0) + n;
    int ldm = (d == 0) ? OUT_F : 2 * OUT_F;

    float am = fmaxf(__int_as_float(g_wamax[e * 3 + d]), 1e-20f);
    float alpha = am * (1.0001f / 16256.0f);
    float inv = 1.0f / alpha, s128 = 128.0f * alpha, i128 = inv * (1.0f / 128.0f);

    int hi[4], lo[4];
#pragma unroll
    for (int j = 0; j < 4; j++) {
        float v = src[(size_t)(kq * 4 + j) * ldm];
        q2(v, i128, s128, inv, hi[j], lo[j]);
    }
    size_t base = (((size_t)((e * 3 + d) * 2) * 256) + n) * 128 + kq * 4;
    *(uint32_t*)&g_wq[base]             = pack4(hi[0], hi[1], hi[2], hi[3]);
    *(uint32_t*)&g_wq[base + 256 * 128] = pack4(lo[0], lo[1], lo[2], lo[3]);
}

// ---------------- kernel 2: int8 3-product mma pipeline + fused sin ----------------
// 16 warps: mi = w>>1 (16-row band), ni = w&1 (16-col half of the 32-col ctile)
__global__ __launch_bounds__(TH, 1) void expert_kernel(
    const float* __restrict__ x,  const float* __restrict__ lat,
    const float* __restrict__ b,  const float* __restrict__ bl,
    float* __restrict__ out)
{
    extern __shared__ __align__(16) char sm[];
    __shared__ int   s_ent[TM];
    __shared__ float s_w[TM];

    int e = blockIdx.y;
    int cnt = g_count[e];
    int m0 = blockIdx.x * TM;
    if (m0 >= cnt) return;
    int rows = min(TM, cnt - m0);
    int tid = threadIdx.x;
    int w = tid >> 5, lane = tid & 31;

    uint32_t smu = smem_u32(sm);
    const char* wqe = g_wq + (size_t)(e * 6) * 256 * 128;

    // scales
    float ax = fmaxf(__int_as_float(g_amax[0]), 1e-20f) * (1.0001f / 16256.0f);
    float al = fmaxf(__int_as_float(g_amax[1]), 1e-20f) * (1.0001f / 16256.0f);
    float aw[3];
#pragma unroll
    for (int d = 0; d < 3; d++)
        aw[d] = fmaxf(__int_as_float(g_wamax[e * 3 + d]), 1e-20f) * (1.0001f / 16256.0f);

    // ---- issue cp.async for ct 0,1 (buf 0,1)
#pragma unroll
    for (int j = 0; j < 2; j++) {
#pragma unroll
        for (int t = 0; t < 3; t++) {
            int u = t * TH + tid;                 // 0..1535
            int mat = u >> 8, rem = u & 255;
            int n = rem >> 3, k16 = rem & 7;
            cp16(smu + BB + (uint32_t)(j * BCH + mat * BMT + n * SROW + k16 * 16),
                 wqe + ((size_t)mat * 256 + j * 32 + n) * 128 + k16 * 16);
        }
        asm volatile("cp.async.commit_group;" ::: "memory");
    }

    if (tid < TM) {
        int ent = (tid < rows) ? g_tok[e * N_TOK + m0 + tid] : 0;
        s_ent[tid] = ent;
        s_w[tid]   = (tid < rows) ? g_wt[e * N_TOK + m0 + tid] : 0.0f;
    }
    __syncthreads();

    // ---- stage A: gather x/lat rows, quantize to int8 hi/lo
#pragma unroll
    for (int s2 = 0; s2 < 2; s2++) {
        const float* src = s2 ? lat : x;
        float alpha = s2 ? al : ax;
        float inv = 1.0f / alpha, s128 = 128.0f * alpha, i128 = inv * (1.0f / 128.0f);
        char* hiT = sm + (s2 ? AL1 : AX1);
        char* loT = sm + (s2 ? AL0 : AX0);
#pragma unroll
        for (int it = 0; it < 8; it++) {
            int idx = it * TH + tid;              // 0..4095
            int m = idx >> 5, kg = (idx & 31) * 4;
            int tok = s_ent[m] & 0xFFFFFF;
            float4 v = *(const float4*)(src + (size_t)tok * IN_F + kg);
            int h0, l0, h1, l1, h2, l2, h3, l3;
            q2(v.x, i128, s128, inv, h0, l0);
            q2(v.y, i128, s128, inv, h1, l1);
            q2(v.z, i128, s128, inv, h2, l2);
            q2(v.w, i128, s128, inv, h3, l3);
            *(uint32_t*)(hiT + m * SROW + kg) = pack4(h0, h1, h2, h3);
            *(uint32_t*)(loT + m * SROW + kg) = pack4(l0, l1, l2, l3);
        }
    }

    int mi = w >> 1, ni = w & 1;
    uint32_t lrow = (uint32_t)((lane & 7) + ((lane >> 3) & 1) * 8);
    uint32_t lcol = (uint32_t)((lane >> 4) * 16);
    uint32_t aof = (uint32_t)(mi * 16 + lrow) * SROW + lcol;
    uint32_t bof = (uint32_t)(ni * 16 + lrow) * SROW + lcol;

    // dequant constants: contribution = 128*s*(128*aS + aM); OMEGA folded into d0
    float c128[3];
#pragma unroll
    for (int d = 0; d < 3; d++) {
        float s = (d == 0 ? ax : al) * aw[d];
        if (d == 0) s *= OMEGA;
        c128[d] = 128.0f * s;
    }

#pragma unroll 1
    for (int ct = 0; ct < 8; ct++) {
        if (ct == 7) asm volatile("cp.async.wait_group 0;" ::: "memory");
        else         asm volatile("cp.async.wait_group 1;" ::: "memory");
        __syncthreads();   // buf (ct-1)%3 now reusable

        if (ct <= 5) {
            int j = ct + 2, buf2 = j % 3;
#pragma unroll
            for (int t = 0; t < 3; t++) {
                int u = t * TH + tid;
                int mat = u >> 8, rem = u & 255;
                int n = rem >> 3, k16 = rem & 7;
                cp16(smu + BB + (uint32_t)(buf2 * BCH + mat * BMT + n * SROW + k16 * 16),
                     wqe + ((size_t)mat * 256 + j * 32 + n) * 128 + k16 * 16);
            }
            asm volatile("cp.async.commit_group;" ::: "memory");
        }

        uint32_t bB = smu + BB + (uint32_t)(ct % 3) * BCH;
        int aS[3][2][4], aM[3][2][4];
#pragma unroll
        for (int d = 0; d < 3; d++)
#pragma unroll
            for (int nf = 0; nf < 2; nf++)
#pragma unroll
                for (int q = 0; q < 4; q++) { aS[d][nf][q] = 0; aM[d][nf][q] = 0; }

#pragma unroll
        for (int kc = 0; kc < 4; kc++) {
            uint32_t kb = (uint32_t)(kc * 32);
            uint32_t X1[4], X0[4], L1[4], L0[4];
            ldsm_x4(X1, smu + AX1 + aof + kb);
            ldsm_x4(X0, smu + AX0 + aof + kb);
            ldsm_x4(L1, smu + AL1 + aof + kb);
            ldsm_x4(L0, smu + AL0 + aof + kb);
#pragma unroll
            for (int d = 0; d < 3; d++) {
                uint32_t B1[4], B0[4];
                ldsm_x4(B1, bB + (uint32_t)(d * 2) * BMT + bof + kb);
                ldsm_x4(B0, bB + (uint32_t)(d * 2 + 1) * BMT + bof + kb);
                const uint32_t (&A1)[4] = d ? L1 : X1;
                const uint32_t (&A0)[4] = d ? L0 : X0;
                mma_s8(aS[d][0], A1, B1[0], B1[2]);
                mma_s8(aM[d][0], A1, B0[0], B0[2]);
                mma_s8(aM[d][0], A0, B1[0], B1[2]);
                mma_s8(aS[d][1], A1, B1[1], B1[3]);
                mma_s8(aM[d][1], A1, B0[1], B0[3]);
                mma_s8(aM[d][1], A0, B1[1], B1[3]);
            }
        }

        // ---- epilogue: IMAD-combine dequant + MUFU sin + gate weight
        {
            int cb0 = ct * 32 + ni * 16 + 2 * (lane & 3);
            float bb[2][2], bs[2][2], bt[2][2];
#pragma unroll
            for (int nf = 0; nf < 2; nf++) {
                float2 B  = *(const float2*)(b  + (size_t)e * OUT_F + cb0 + nf * 8);
                float2 S  = *(const float2*)(bl + (size_t)e * 2 * OUT_F + cb0 + nf * 8);
                float2 T  = *(const float2*)(bl + (size_t)e * 2 * OUT_F + OUT_F + cb0 + nf * 8);
                bb[nf][0] = B.x * OMEGA;
                bb[nf][1] = B.y * OMEGA;
                bs[nf][0] = S.x;
                bs[nf][1] = S.y;
                bt[nf][0] = T.x;
                bt[nf][1] = T.y;
            }
#pragma unroll
            for (int hh = 0; hh < 2; hh++) {
                int row = mi * 16 + (lane >> 2) + 8 * hh;
                if (row < rows) {
                    int ent = s_ent[row];
                    int tok = ent & 0xFFFFFF, sl = (ent >> 24) & 1;
                    float wt = s_w[row];
                    float* gp = sl ? &g_part[tok][cb0]
                                   : out + (size_t)tok * OUT_F + cb0;
#pragma unroll
                    for (int nf = 0; nf < 2; nf++) {
                        float2 o;
#pragma unroll
                        for (int q = 0; q < 2; q++) {
                            int i2 = 2 * hh + q;
                            int C0 = aS[0][nf][i2] * 128 + aM[0][nf][i2];
                            int C1 = aS[1][nf][i2] * 128 + aM[1][nf][i2];
                            int C2 = aS[2][nf][i2] * 128 + aM[2][nf][i2];
                            float hv30 = fmaf(__int2float_rn(C0), c128[0], bb[nf][q]);
                            float sc   = fmaf(__int2float_rn(C1), c128[1], bs[nf][q]);
                            float sh   = fmaf(__int2float_rn(C2), c128[2], bt[nf][q]);
                            float ov = wt * __sinf(fmaf(hv30, sc, sh));
                            if (q) o.y = ov; else o.x = ov;
                        }
                        *(float2*)(gp + nf * 8) = o;
                    }
                }
            }
        }
    }
}

// ---------------- kernel 3: combine (out += slot-1 partial) ----------------
__global__ void combine_kernel(float* __restrict__ out) {
    size_t i = (size_t)blockIdx.x * blockDim.x + threadIdx.x;
    const float4* p1 = (const float4*)&g_part[0][0];
    float4 a = ((const float4*)out)[i];
    float4 c = p1[i];
    ((float4*)out)[i] = make_float4(a.x + c.x, a.y + c.y, a.z + c.z, a.w + c.w);
}

// ---------------- launch ----------------
extern "C" void kernel_launch(void* const* d_in, const int* in_sizes, int n_in,
                              void* d_out, int out_size) {
    const float* x   = (const float*)d_in[0];
    const float* lat = (const float*)d_in[1];
    const float* gw  = (const float*)d_in[2];
    const float* gb  = (const float*)d_in[3];
    const float* W   = (const float*)d_in[4];
    const float* b   = (const float*)d_in[5];
    const float* Wl  = (const float*)d_in[6];
    const float* bl  = (const float*)d_in[7];
    float* out = (float*)d_out;

    cudaFuncSetAttribute(expert_kernel,
                         cudaFuncAttributeMaxDynamicSharedMemorySize, SMEM_BYTES);

    initw_kernel<<<24, 256>>>(W, Wl);
    route_kernel<<<N_TOK / 8, 256>>>(x, lat, gw, gb, out);
    scatter_kernel<<<32, 256>>>();
    wq_kernel<<<768, 256>>>(W, Wl);
    expert_kernel<<<dim3(N_TOK / TM, NEXP), TH, SMEM_BYTES>>>(x, lat, b, bl, out);
    combine_kernel<<<(N_TOK * OUT_F / 4) / 256, 256>>>(out);
}